// round 15
// baseline (speedup 1.0000x reference)
#include <cuda_runtime.h>
#include <cuda_fp16.h>
#include <cstdint>

#define BATCH  4096
#define SEQ    16
#define EMBED  512
#define HIDDEN 1024
#define HEADS  16
#define DHEAD  64
#define VOCAB  50257
#define VPAD   50304                    // 393 * 128
#define NV_TILES 393
#define NT_TILES 32

// ---------------- device scratch (no cudaMalloc allowed) ----------------
__device__ float  g_Q[(size_t)BATCH * HIDDEN];
__device__ __half g_Kv[(size_t)VPAD * HIDDEN];
__device__ __half g_Vv[(size_t)VPAD * HIDDEN];
__device__ __half g_emb_h[(size_t)VPAD * EMBED];                 // pad rows stay 0
__device__ __half g_W_h[3u * HIDDEN * EMBED];                    // WQ,WK,WV
__device__ int    g_flags[VPAD];
__device__ int    g_list[VPAD];
__device__ int    g_cnt[1];

// ---------------- helpers ----------------
__device__ __forceinline__ uint32_t smem_u32(const void* p) {
    uint32_t a;
    asm("{ .reg .u64 t; cvta.to.shared.u64 t, %1; cvt.u32.u64 %0, t; }"
        : "=r"(a) : "l"(p));
    return a;
}
__device__ __forceinline__ void cpa16(uint32_t dst, const void* src) {
    asm volatile("cp.async.cg.shared.global [%0], [%1], 16;"
                 :: "r"(dst), "l"(src) : "memory");
}
#define CP_COMMIT() asm volatile("cp.async.commit_group;" ::: "memory")
#define CP_WAIT(n)  asm volatile("cp.async.wait_group %0;" :: "n"(n) : "memory")

__device__ __forceinline__ void ldm4(uint32_t& r0, uint32_t& r1,
                                     uint32_t& r2, uint32_t& r3, uint32_t a) {
    asm volatile("ldmatrix.sync.aligned.m8n8.x4.shared.b16 {%0,%1,%2,%3}, [%4];"
                 : "=r"(r0), "=r"(r1), "=r"(r2), "=r"(r3) : "r"(a));
}
__device__ __forceinline__ void ldm2t(uint32_t& r0, uint32_t& r1, uint32_t a) {
    asm volatile("ldmatrix.sync.aligned.m8n8.x2.trans.shared.b16 {%0,%1}, [%2];"
                 : "=r"(r0), "=r"(r1) : "r"(a));
}
__device__ __forceinline__ void mma16816(float* d,
                                         uint32_t a0, uint32_t a1, uint32_t a2, uint32_t a3,
                                         uint32_t b0, uint32_t b1) {
    asm volatile(
        "mma.sync.aligned.m16n8k16.row.col.f32.f16.f16.f32 "
        "{%0,%1,%2,%3}, {%4,%5,%6,%7}, {%8,%9}, {%0,%1,%2,%3};"
        : "+f"(d[0]), "+f"(d[1]), "+f"(d[2]), "+f"(d[3])
        : "r"(a0), "r"(a1), "r"(a2), "r"(a3), "r"(b0), "r"(b1));
}

// ---------------- compaction chain (marks c AND t tokens) ----------------
__global__ __launch_bounds__(256) void zero_kernel() {
    int i = blockIdx.x * blockDim.x + threadIdx.x;
    if (i < VPAD) g_flags[i] = 0;
    if (i == 0) g_cnt[0] = 0;
}
__global__ __launch_bounds__(256) void mark_kernel(const int* __restrict__ c,
                                                   const int* __restrict__ t) {
    int i = blockIdx.x * blockDim.x + threadIdx.x;
    if (i < BATCH * SEQ) g_flags[c[i]] = 1;
    if (i < BATCH)       g_flags[t[i]] = 1;
}
__global__ __launch_bounds__(256) void compact_kernel() {
    int i = blockIdx.x * blockDim.x + threadIdx.x;
    if (i < VPAD && g_flags[i]) {
        int pos = atomicAdd(g_cnt, 1);
        g_list[pos] = i;
    }
}

// ---------------- fp32 -> fp16 converts (full emb — R13 proven) ----------
__global__ __launch_bounds__(256) void conv_emb_kernel(const float* __restrict__ src,
                                                       int n4) {
    int i = blockIdx.x * blockDim.x + threadIdx.x;
    if (i >= n4) return;
    float4 v = ((const float4*)src)[i];
    ((__half2*)g_emb_h)[2 * i]     = __floats2half2_rn(v.x, v.y);
    ((__half2*)g_emb_h)[2 * i + 1] = __floats2half2_rn(v.z, v.w);
}
__global__ __launch_bounds__(256) void conv_w_kernel(const float* __restrict__ WQ,
                                                     const float* __restrict__ WK,
                                                     const float* __restrict__ WV,
                                                     int n4w) {
    int i = blockIdx.x * blockDim.x + threadIdx.x;
    if (i >= 3 * n4w) return;
    int sel = i / n4w;
    int j   = i - sel * n4w;
    const float* src = (sel == 0) ? WQ : (sel == 1) ? WK : WV;
    float4 v = ((const float4*)src)[j];
    __half2* dst = (__half2*)(g_W_h + (size_t)sel * HIDDEN * EMBED);
    dst[2 * j]     = __floats2half2_rn(v.x, v.y);
    dst[2 * j + 1] = __floats2half2_rn(v.z, v.w);
}

// ---------------- fp16 mma.sync GEMM (128x128, KC32, occ 2) ----------------
// inner loop: ALL fragment loads for both ks steps hoisted before MMAs
#define ROWB    80
#define TILEX   (128 * ROWB)            // 10240 B
#define STAGEB  (2 * TILEX)             // 20480 B
#define NSTAGE  4
#define SMEM_DYN (NSTAGE * STAGEB)      // 81920 B

__global__ __launch_bounds__(256, 2) void gemm_mma_kernel(
    const int* __restrict__ t,
    const float* __restrict__ bQ, const float* __restrict__ bK,
    const float* __restrict__ bV)
{
    extern __shared__ char smdyn[];
    __shared__ float bias_s[128];
    __shared__ int   rowid_s[128];

    const int tid  = threadIdx.x;
    const int lane = tid & 31;
    const int w    = tid >> 5;

    const int  nt    = blockIdx.x;             // 0..15
    const int  by    = blockIdx.y;             // 0..424
    const bool is_t  = (by >= NV_TILES);
    const int  m0    = (is_t ? by - NV_TILES : by) * 128;

    if (is_t && nt >= 8) return;
    int cnt = 0;
    if (!is_t) {
        cnt = g_cnt[0];
        if (m0 >= cnt) return;
    }

    const int  msel  = is_t ? 0 : ((nt < 8) ? 1 : 2);
    const float* bias = is_t ? bQ : ((nt < 8) ? bK : bV);
    __half* CoutH = is_t ? nullptr : ((nt < 8) ? g_Kv : g_Vv);
    const int ncol0 = (nt & 7) * 128;

    const uint32_t smb = smem_u32(smdyn);

    if (tid < 128) {
        bias_s[tid]  = bias[ncol0 + tid];
        const int li = m0 + tid;
        rowid_s[tid] = is_t ? li : ((li < cnt) ? g_list[li] : (VPAD - 1));
    }

    const int rr = tid >> 1;
    const int ss = (tid & 1) * 2;
    const int lr = m0 + rr;
    const int arow = is_t ? t[lr] : ((lr < cnt) ? g_list[lr] : (VPAD - 1));
    const __half* pa = g_emb_h + (size_t)arow * EMBED + ss * 8;
    const __half* pb = g_W_h + (size_t)msel * HIDDEN * EMBED
                     + (size_t)(ncol0 + rr) * EMBED + ss * 8;
    const uint32_t dd = (uint32_t)(rr * ROWB + ss * 16);

    auto issue = [&](int k) {
        const uint32_t d0 = smb + (uint32_t)(k & (NSTAGE - 1)) * STAGEB + dd;
        const int ke = k * 32;
        cpa16(d0,              pa + ke);
        cpa16(d0 + 16,         pa + ke + 8);
        cpa16(d0 + TILEX,      pb + ke);
        cpa16(d0 + TILEX + 16, pb + ke + 8);
        CP_COMMIT();
    };

    const int w_m = w & 3;
    const int w_n = w >> 2;
    const int lrow = lane & 15;
    const int lhalf = (lane >> 4) * 16;
    uint32_t aBase[2], bBase[4];
#pragma unroll
    for (int mt = 0; mt < 2; mt++)
        aBase[mt] = smb + (uint32_t)((w_m * 32 + mt * 16 + lrow) * ROWB + lhalf);
#pragma unroll
    for (int g = 0; g < 4; g++)
        bBase[g] = smb + TILEX + (uint32_t)((w_n * 64 + g * 16 + lrow) * ROWB + lhalf);

    float acc[2][8][4];
#pragma unroll
    for (int mt = 0; mt < 2; mt++)
#pragma unroll
        for (int f = 0; f < 8; f++)
#pragma unroll
            for (int q = 0; q < 4; q++) acc[mt][f][q] = 0.0f;

    issue(0); issue(1); issue(2);

#pragma unroll 1
    for (int k = 0; k < 16; k++) {
        CP_WAIT(2);
        __syncthreads();
        if (k + 3 < 16) issue(k + 3);
        else            CP_COMMIT();

        const uint32_t boff = (uint32_t)(k & (NSTAGE - 1)) * STAGEB;

        // ---- hoisted fragment loads for BOTH ks steps (12 ldm4) ----
        uint32_t a[2][2][4], b[2][4][4];       // [ks][mt|g][4]
#pragma unroll
        for (int ks = 0; ks < 2; ks++) {
            const uint32_t off = boff + ks * 32;
#pragma unroll
            for (int mt = 0; mt < 2; mt++)
                ldm4(a[ks][mt][0], a[ks][mt][1], a[ks][mt][2], a[ks][mt][3],
                     aBase[mt] + off);
#pragma unroll
            for (int g = 0; g < 4; g++)
                ldm4(b[ks][g][0], b[ks][g][1], b[ks][g][2], b[ks][g][3],
                     bBase[g] + off);
        }
        // ---- all 64 MMAs ----
#pragma unroll
        for (int ks = 0; ks < 2; ks++)
#pragma unroll
            for (int mt = 0; mt < 2; mt++)
#pragma unroll
                for (int g = 0; g < 4; g++)
#pragma unroll
                    for (int j = 0; j < 2; j++)
                        mma16816(acc[mt][g * 2 + j],
                                 a[ks][mt][0], a[ks][mt][1], a[ks][mt][2], a[ks][mt][3],
                                 b[ks][g][j], b[ks][g][j + 2]);
    }

#pragma unroll
    for (int mt = 0; mt < 2; mt++) {
        const int rl = w_m * 32 + mt * 16 + (lane >> 2);
        const int row0 = rowid_s[rl];
        const int row1 = rowid_s[rl + 8];
#pragma unroll
        for (int g = 0; g < 4; g++)
#pragma unroll
            for (int j = 0; j < 2; j++) {
                const int cl = w_n * 64 + g * 16 + j * 8 + (lane & 3) * 2;
                const float* d = acc[mt][g * 2 + j];
                const float b0 = bias_s[cl], b1 = bias_s[cl + 1];
                if (CoutH) {
                    __half2 v0 = __floats2half2_rn(d[0] + b0, d[1] + b1);
                    __half2 v1 = __floats2half2_rn(d[2] + b0, d[3] + b1);
                    *(__half2*)(CoutH + (size_t)row0 * HIDDEN + ncol0 + cl) = v0;
                    *(__half2*)(CoutH + (size_t)row1 * HIDDEN + ncol0 + cl) = v1;
                } else {
                    float2 v0 = make_float2(d[0] + b0, d[1] + b1);
                    float2 v1 = make_float2(d[2] + b0, d[3] + b1);
                    *(float2*)(g_Q + (size_t)row0 * HIDDEN + ncol0 + cl) = v0;
                    *(float2*)(g_Q + (size_t)row1 * HIDDEN + ncol0 + cl) = v1;
                }
            }
    }
}

// -------- attention: all-tensor-core (scores + AV), fp32 softmax -----------
#define ATT_QHI  0                       // half Qhi[16][72]   = 2304
#define ATT_QLO  2304                    // half Qlo[16][72]   = 2304
#define ATT_SC   4608                    // float Sc[256][17]  = 17408
#define ATT_AHI  (ATT_SC + 17408)        // half Ahi[16][264]  = 8448
#define ATT_ALO  (ATT_AHI + 8448)        // half Alo[16][264]  = 8448
#define ATT_VSM  (ATT_ALO + 8448)        // half Vsm[256][72]  = 36864
#define ATT_KSM  (ATT_VSM + 36864)       // half Ksm[256][72]  = 36864
#define ATT_CS   (ATT_KSM + 36864)       // int cs[16]         = 64
#define SMEM_ATT (ATT_CS + 64)           // 112704
#define AROWB 528
#define VROWB 144

__global__ __launch_bounds__(256) void attn_kernel(const int* __restrict__ t,
                                                   const int* __restrict__ c,
                                                   float* __restrict__ out_target,
                                                   float* __restrict__ out_ctx)
{
    extern __shared__ char sm[];
    float (*Sc)[17] = (float(*)[17])(sm + ATT_SC);
    int* cs = (int*)(sm + ATT_CS);
    const uint32_t smb = smem_u32(sm);

    const int b    = blockIdx.x;
    const int tid  = threadIdx.x;
    const int lane = tid & 31;
    const int w    = tid >> 5;

    if (tid < SEQ) cs[tid] = c[b * SEQ + tid];

    // Q hi/lo split into smem (exact)
    {
        const int h = tid >> 4;
        const int d = (tid & 15) * 4;
        float4 v = *(const float4*)(g_Q + (size_t)b * HIDDEN + h * DHEAD + d);
        __half h0 = __float2half_rn(v.x), h1 = __float2half_rn(v.y);
        __half h2 = __float2half_rn(v.z), h3 = __float2half_rn(v.w);
        __half2* qh = (__half2*)(sm + ATT_QHI + h * VROWB + d * 2);
        __half2* ql = (__half2*)(sm + ATT_QLO + h * VROWB + d * 2);
        qh[0] = __halves2half2(h0, h1);
        qh[1] = __halves2half2(h2, h3);
        ql[0] = __halves2half2(__float2half_rn(v.x - __half2float(h0)),
                               __float2half_rn(v.y - __half2float(h1)));
        ql[1] = __halves2half2(__float2half_rn(v.z - __half2float(h2)),
                               __float2half_rn(v.w - __half2float(h3)));
    }

    // target_vector[b] = V-table row of token t[b]
    {
        const int tb = t[b];
        uint2 raw = ((const uint2*)(g_Vv + (size_t)tb * HIDDEN))[tid];
        float2 f0 = __half22float2(*(__half2*)&raw.x);
        float2 f1 = __half22float2(*(__half2*)&raw.y);
        *(float4*)(out_target + (size_t)b * HIDDEN + tid * 4) =
            make_float4(f0.x, f0.y, f1.x, f1.y);
    }
    __syncthreads();

    // K and V staging
#pragma unroll
    for (int j = 0; j < 16; j++) {
        const int idx = tid + j * 256;
        const int row = idx >> 4;
        const int cc  = idx & 15;
        const size_t gofs = (size_t)cs[row >> 4] * HIDDEN + (row & 15) * DHEAD + cc * 4;
        *(uint2*)(sm + ATT_KSM + row * VROWB + cc * 8) = *(const uint2*)(g_Kv + gofs);
        *(uint2*)(sm + ATT_VSM + row * VROWB + cc * 8) = *(const uint2*)(g_Vv + gofs);
    }
    __syncthreads();

    // scores via mma
    {
        const uint32_t aH = smb + ATT_QHI + (lane & 15) * VROWB + (lane >> 4) * 16;
        const uint32_t aL = smb + ATT_QLO + (lane & 15) * VROWB + (lane >> 4) * 16;
        uint32_t bB[2];
#pragma unroll
        for (int g16 = 0; g16 < 2; g16++)
            bB[g16] = smb + ATT_KSM
                    + (uint32_t)((w * 32 + g16 * 16 + (lane & 15)) * VROWB)
                    + (lane >> 4) * 16;

        float acc[2][2][4];
#pragma unroll
        for (int g16 = 0; g16 < 2; g16++)
#pragma unroll
            for (int j = 0; j < 2; j++)
#pragma unroll
                for (int q = 0; q < 4; q++) acc[g16][j][q] = 0.0f;

#pragma unroll
        for (int kk = 0; kk < 4; kk++) {
            uint32_t ah0, ah1, ah2, ah3, al0, al1, al2, al3;
            ldm4(ah0, ah1, ah2, ah3, aH + kk * 32);
            ldm4(al0, al1, al2, al3, aL + kk * 32);
#pragma unroll
            for (int g16 = 0; g16 < 2; g16++) {
                uint32_t b0, b1, b2, b3;
                ldm4(b0, b1, b2, b3, bB[g16] + kk * 32);
                mma16816(acc[g16][0], ah0, ah1, ah2, ah3, b0, b2);
                mma16816(acc[g16][1], ah0, ah1, ah2, ah3, b1, b3);
                mma16816(acc[g16][0], al0, al1, al2, al3, b0, b2);
                mma16816(acc[g16][1], al0, al1, al2, al3, b1, b3);
            }
        }

        const int h0 = lane >> 2;
#pragma unroll
        for (int g16 = 0; g16 < 2; g16++)
#pragma unroll
            for (int j = 0; j < 2; j++) {
                const int sg = w * 32 + g16 * 16 + j * 8 + (lane & 3) * 2;
                const int s = sg >> 4, g = sg & 15;
                const float* d = acc[g16][j];
                Sc[s * 16 + h0][g]     = d[0] * 0.125f;
                Sc[s * 16 + h0][g + 1] = d[1] * 0.125f;
                Sc[s * 16 + h0 + 8][g]     = d[2] * 0.125f;
                Sc[s * 16 + h0 + 8][g + 1] = d[3] * 0.125f;
            }
    }
    __syncthreads();

    // softmax + A hi/lo
    {
        const int s = tid >> 4, h = tid & 15;
        float v[16];
        float* row = Sc[tid];
        float mx = -1e30f;
#pragma unroll
        for (int g = 0; g < 16; g++) { v[g] = row[g]; mx = fmaxf(mx, v[g]); }
        float sum = 0.0f;
#pragma unroll
        for (int g = 0; g < 16; g++) { v[g] = __expf(v[g] - mx); sum += v[g]; }
        float inv = 1.0f / sum;
        __half2* dh = (__half2*)(sm + ATT_AHI + h * AROWB + s * 32);
        __half2* dl = (__half2*)(sm + ATT_ALO + h * AROWB + s * 32);
#pragma unroll
        for (int gp = 0; gp < 8; gp++) {
            float a0 = v[2 * gp] * inv, a1 = v[2 * gp + 1] * inv;
            __half h0 = __float2half_rn(a0), h1 = __float2half_rn(a1);
            float l0 = a0 - __half2float(h0), l1 = a1 - __half2float(h1);
            dh[gp] = __halves2half2(h0, h1);
            dl[gp] = __halves2half2(__float2half_rn(l0), __float2half_rn(l1));
        }
    }
    __syncthreads();

    // AV via mma
    {
        const uint32_t aH = smb + ATT_AHI + (lane & 15) * AROWB + (lane >> 4) * 16;
        const uint32_t aL = smb + ATT_ALO + (lane & 15) * AROWB + (lane >> 4) * 16;
        const uint32_t bB = smb + ATT_VSM + (lane & 15) * VROWB + w * 16;

        float acc[4] = {0.f, 0.f, 0.f, 0.f};
#pragma unroll
        for (int kk = 0; kk < 16; kk++) {
            uint32_t a0, a1, a2, a3, l0, l1, l2, l3, b0, b1;
            ldm4(a0, a1, a2, a3, aH + kk * 32);
            ldm4(l0, l1, l2, l3, aL + kk * 32);
            ldm2t(b0, b1, bB + kk * 16 * VROWB);
            mma16816(acc, a0, a1, a2, a3, b0, b1);
            mma16816(acc, l0, l1, l2, l3, b0, b1);
        }

        const int h0 = lane >> 2;
        const int dcol = w * 8 + (lane & 3) * 2;
        float* o = out_ctx + (size_t)b * HIDDEN;
        *(float2*)(o + h0 * DHEAD + dcol)       = make_float2(acc[0], acc[1]);
        *(float2*)(o + (h0 + 8) * DHEAD + dcol) = make_float2(acc[2], acc[3]);
    }
}

// ---------------------------------------------------------------------------
extern "C" void kernel_launch(void* const* d_in, const int* in_sizes, int n_in,
                              void* d_out, int out_size)
{
    const int*   t   = (const int*)d_in[0];
    const int*   c   = (const int*)d_in[1];
    const float* emb = (const float*)d_in[2];
    const float* WQ  = (const float*)d_in[3];
    const float* bQ  = (const float*)d_in[4];
    const float* WK  = (const float*)d_in[5];
    const float* bK  = (const float*)d_in[6];
    const float* WV  = (const float*)d_in[7];
    const float* bV  = (const float*)d_in[8];
    float* out = (float*)d_out;

    float* out_target = out;
    float* out_ctx    = out + (size_t)BATCH * HIDDEN;

    // used-token compaction (c AND t)
    {
        int gz = (VPAD + 255) / 256;
        zero_kernel<<<gz, 256>>>();
        mark_kernel<<<(BATCH * SEQ + 255) / 256, 256>>>(c, t);
        compact_kernel<<<gz, 256>>>();
    }

    // fp32 -> fp16 converts (full emb — reverted; used-rows variant regressed)
    {
        int n4e = (VOCAB * EMBED) / 4;
        conv_emb_kernel<<<(n4e + 255) / 256, 256>>>(emb, n4e);
        int n4w = (HIDDEN * EMBED) / 4;
        conv_w_kernel<<<(3 * n4w + 255) / 256, 256>>>(WQ, WK, WV, n4w);
    }

    // GEMMs: K/V for used tokens (scattered) + Q for targets
    cudaFuncSetAttribute(gemm_mma_kernel,
                         cudaFuncAttributeMaxDynamicSharedMemorySize, SMEM_DYN);
    {
        dim3 grid(16, NV_TILES + NT_TILES);
        gemm_mma_kernel<<<grid, 256, SMEM_DYN>>>(t, bQ, bK, bV);
    }

    // attention (all tensor-core) + target_vector gather
    cudaFuncSetAttribute(attn_kernel,
                         cudaFuncAttributeMaxDynamicSharedMemorySize, SMEM_ATT);
    attn_kernel<<<BATCH, 256, SMEM_ATT>>>(t, c, out_target, out_ctx);
}

// round 16
// speedup vs baseline: 1.0022x; 1.0022x over previous
#include <cuda_runtime.h>
#include <cuda_fp16.h>
#include <cstdint>

#define BATCH  4096
#define SEQ    16
#define EMBED  512
#define HIDDEN 1024
#define HEADS  16
#define DHEAD  64
#define VOCAB  50257
#define VPAD   50304                    // 393 * 128
#define NV_TILES 393
#define NT_TILES 32

// ---------------- device scratch (no cudaMalloc allowed) ----------------
__device__ float  g_Q[(size_t)BATCH * HIDDEN];
__device__ __half g_Kv[(size_t)VPAD * HIDDEN];
__device__ __half g_Vv[(size_t)VPAD * HIDDEN];
__device__ __half g_emb_h[(size_t)VPAD * EMBED];                 // pad rows stay 0
__device__ __half g_W_h[3u * HIDDEN * EMBED];                    // WQ,WK,WV
__device__ int    g_flags[VPAD];
__device__ int    g_list[VPAD];
__device__ int    g_cnt[1];

// ---------------- helpers ----------------
__device__ __forceinline__ uint32_t smem_u32(const void* p) {
    uint32_t a;
    asm("{ .reg .u64 t; cvta.to.shared.u64 t, %1; cvt.u32.u64 %0, t; }"
        : "=r"(a) : "l"(p));
    return a;
}
__device__ __forceinline__ void cpa16(uint32_t dst, const void* src) {
    asm volatile("cp.async.cg.shared.global [%0], [%1], 16;"
                 :: "r"(dst), "l"(src) : "memory");
}
#define CP_COMMIT() asm volatile("cp.async.commit_group;" ::: "memory")
#define CP_WAIT(n)  asm volatile("cp.async.wait_group %0;" :: "n"(n) : "memory")

__device__ __forceinline__ void ldm4(uint32_t& r0, uint32_t& r1,
                                     uint32_t& r2, uint32_t& r3, uint32_t a) {
    asm volatile("ldmatrix.sync.aligned.m8n8.x4.shared.b16 {%0,%1,%2,%3}, [%4];"
                 : "=r"(r0), "=r"(r1), "=r"(r2), "=r"(r3) : "r"(a));
}
__device__ __forceinline__ void ldm2t(uint32_t& r0, uint32_t& r1, uint32_t a) {
    asm volatile("ldmatrix.sync.aligned.m8n8.x2.trans.shared.b16 {%0,%1}, [%2];"
                 : "=r"(r0), "=r"(r1) : "r"(a));
}
__device__ __forceinline__ void mma16816(float* d,
                                         uint32_t a0, uint32_t a1, uint32_t a2, uint32_t a3,
                                         uint32_t b0, uint32_t b1) {
    asm volatile(
        "mma.sync.aligned.m16n8k16.row.col.f32.f16.f16.f32 "
        "{%0,%1,%2,%3}, {%4,%5,%6,%7}, {%8,%9}, {%0,%1,%2,%3};"
        : "+f"(d[0]), "+f"(d[1]), "+f"(d[2]), "+f"(d[3])
        : "r"(a0), "r"(a1), "r"(a2), "r"(a3), "r"(b0), "r"(b1));
}

// ------- fused prep: zero flags/cnt + fp32->fp16 emb + weights ------------
__global__ __launch_bounds__(256) void prep_kernel(
    const float* __restrict__ emb,
    const float* __restrict__ WQ, const float* __restrict__ WK,
    const float* __restrict__ WV, int n4e, int n4w)
{
    const int i = blockIdx.x * blockDim.x + threadIdx.x;
    if (i < VPAD) {
        g_flags[i] = 0;
        if (i == 0) g_cnt[0] = 0;
    }
    if (i < n4e) {
        float4 v = ((const float4*)emb)[i];
        ((__half2*)g_emb_h)[2 * i]     = __floats2half2_rn(v.x, v.y);
        ((__half2*)g_emb_h)[2 * i + 1] = __floats2half2_rn(v.z, v.w);
    } else {
        const int j = i - n4e;
        if (j < 3 * n4w) {
            const int sel = j / n4w;
            const int jj  = j - sel * n4w;
            const float* src = (sel == 0) ? WQ : (sel == 1) ? WK : WV;
            float4 v = ((const float4*)src)[jj];
            __half2* dst = (__half2*)(g_W_h + (size_t)sel * HIDDEN * EMBED);
            dst[2 * jj]     = __floats2half2_rn(v.x, v.y);
            dst[2 * jj + 1] = __floats2half2_rn(v.z, v.w);
        }
    }
}

// ---------------- compaction (marks c AND t tokens) ----------------
__global__ __launch_bounds__(256) void mark_kernel(const int* __restrict__ c,
                                                   const int* __restrict__ t) {
    int i = blockIdx.x * blockDim.x + threadIdx.x;
    if (i < BATCH * SEQ) g_flags[c[i]] = 1;
    if (i < BATCH)       g_flags[t[i]] = 1;
}
__global__ __launch_bounds__(256) void compact_kernel() {
    int i = blockIdx.x * blockDim.x + threadIdx.x;
    if (i < VPAD && g_flags[i]) {
        int pos = atomicAdd(g_cnt, 1);
        g_list[pos] = i;
    }
}

// ---------------- fp16 mma.sync GEMM (R14 shape: 128x128, KC32, occ 2) -----
#define ROWB    80
#define TILEX   (128 * ROWB)            // 10240 B
#define STAGEB  (2 * TILEX)             // 20480 B
#define NSTAGE  4
#define SMEM_DYN (NSTAGE * STAGEB)      // 81920 B

__global__ __launch_bounds__(256, 2) void gemm_mma_kernel(
    const int* __restrict__ t,
    const float* __restrict__ bQ, const float* __restrict__ bK,
    const float* __restrict__ bV)
{
    extern __shared__ char smdyn[];
    __shared__ float bias_s[128];
    __shared__ int   rowid_s[128];

    const int tid  = threadIdx.x;
    const int lane = tid & 31;
    const int w    = tid >> 5;

    const int  nt    = blockIdx.x;             // 0..15
    const int  by    = blockIdx.y;             // 0..424
    const bool is_t  = (by >= NV_TILES);
    const int  m0    = (is_t ? by - NV_TILES : by) * 128;

    if (is_t && nt >= 8) return;
    int cnt = 0;
    if (!is_t) {
        cnt = g_cnt[0];
        if (m0 >= cnt) return;
    }

    const int  msel  = is_t ? 0 : ((nt < 8) ? 1 : 2);
    const float* bias = is_t ? bQ : ((nt < 8) ? bK : bV);
    __half* CoutH = is_t ? nullptr : ((nt < 8) ? g_Kv : g_Vv);
    const int ncol0 = (nt & 7) * 128;

    const uint32_t smb = smem_u32(smdyn);

    if (tid < 128) {
        bias_s[tid]  = bias[ncol0 + tid];
        const int li = m0 + tid;
        rowid_s[tid] = is_t ? li : ((li < cnt) ? g_list[li] : (VPAD - 1));
    }

    const int rr = tid >> 1;
    const int ss = (tid & 1) * 2;
    const int lr = m0 + rr;
    const int arow = is_t ? t[lr] : ((lr < cnt) ? g_list[lr] : (VPAD - 1));
    const __half* pa = g_emb_h + (size_t)arow * EMBED + ss * 8;
    const __half* pb = g_W_h + (size_t)msel * HIDDEN * EMBED
                     + (size_t)(ncol0 + rr) * EMBED + ss * 8;
    const uint32_t dd = (uint32_t)(rr * ROWB + ss * 16);

    auto issue = [&](int k) {
        const uint32_t d0 = smb + (uint32_t)(k & (NSTAGE - 1)) * STAGEB + dd;
        const int ke = k * 32;
        cpa16(d0,              pa + ke);
        cpa16(d0 + 16,         pa + ke + 8);
        cpa16(d0 + TILEX,      pb + ke);
        cpa16(d0 + TILEX + 16, pb + ke + 8);
        CP_COMMIT();
    };

    const int w_m = w & 3;
    const int w_n = w >> 2;
    const int lrow = lane & 15;
    const int lhalf = (lane >> 4) * 16;
    uint32_t aBase[2], bBase[4];
#pragma unroll
    for (int mt = 0; mt < 2; mt++)
        aBase[mt] = smb + (uint32_t)((w_m * 32 + mt * 16 + lrow) * ROWB + lhalf);
#pragma unroll
    for (int g = 0; g < 4; g++)
        bBase[g] = smb + TILEX + (uint32_t)((w_n * 64 + g * 16 + lrow) * ROWB + lhalf);

    float acc[2][8][4];
#pragma unroll
    for (int mt = 0; mt < 2; mt++)
#pragma unroll
        for (int f = 0; f < 8; f++)
#pragma unroll
            for (int q = 0; q < 4; q++) acc[mt][f][q] = 0.0f;

    issue(0); issue(1); issue(2);

#pragma unroll 1
    for (int k = 0; k < 16; k++) {
        CP_WAIT(2);
        __syncthreads();
        if (k + 3 < 16) issue(k + 3);
        else            CP_COMMIT();

        const uint32_t boff = (uint32_t)(k & (NSTAGE - 1)) * STAGEB;
#pragma unroll
        for (int ks = 0; ks < 2; ks++) {
            const uint32_t off = boff + ks * 32;
            uint32_t a[2][4], b[4][4];
#pragma unroll
            for (int mt = 0; mt < 2; mt++)
                ldm4(a[mt][0], a[mt][1], a[mt][2], a[mt][3], aBase[mt] + off);
#pragma unroll
            for (int g = 0; g < 4; g++)
                ldm4(b[g][0], b[g][1], b[g][2], b[g][3], bBase[g] + off);
#pragma unroll
            for (int mt = 0; mt < 2; mt++)
#pragma unroll
                for (int g = 0; g < 4; g++)
#pragma unroll
                    for (int j = 0; j < 2; j++)
                        mma16816(acc[mt][g * 2 + j],
                                 a[mt][0], a[mt][1], a[mt][2], a[mt][3],
                                 b[g][j], b[g][j + 2]);
        }
    }

#pragma unroll
    for (int mt = 0; mt < 2; mt++) {
        const int rl = w_m * 32 + mt * 16 + (lane >> 2);
        const int row0 = rowid_s[rl];
        const int row1 = rowid_s[rl + 8];
#pragma unroll
        for (int g = 0; g < 4; g++)
#pragma unroll
            for (int j = 0; j < 2; j++) {
                const int cl = w_n * 64 + g * 16 + j * 8 + (lane & 3) * 2;
                const float* d = acc[mt][g * 2 + j];
                const float b0 = bias_s[cl], b1 = bias_s[cl + 1];
                if (CoutH) {
                    __half2 v0 = __floats2half2_rn(d[0] + b0, d[1] + b1);
                    __half2 v1 = __floats2half2_rn(d[2] + b0, d[3] + b1);
                    *(__half2*)(CoutH + (size_t)row0 * HIDDEN + ncol0 + cl) = v0;
                    *(__half2*)(CoutH + (size_t)row1 * HIDDEN + ncol0 + cl) = v1;
                } else {
                    float2 v0 = make_float2(d[0] + b0, d[1] + b1);
                    float2 v1 = make_float2(d[2] + b0, d[3] + b1);
                    *(float2*)(g_Q + (size_t)row0 * HIDDEN + ncol0 + cl) = v0;
                    *(float2*)(g_Q + (size_t)row1 * HIDDEN + ncol0 + cl) = v1;
                }
            }
    }
}

// -------- attention: all-tensor-core (scores + AV), fp32 softmax -----------
#define ATT_QHI  0                       // half Qhi[16][72]   = 2304
#define ATT_QLO  2304                    // half Qlo[16][72]   = 2304
#define ATT_SC   4608                    // float Sc[256][17]  = 17408
#define ATT_AHI  (ATT_SC + 17408)        // half Ahi[16][264]  = 8448
#define ATT_ALO  (ATT_AHI + 8448)        // half Alo[16][264]  = 8448
#define ATT_VSM  (ATT_ALO + 8448)        // half Vsm[256][72]  = 36864
#define ATT_KSM  (ATT_VSM + 36864)       // half Ksm[256][72]  = 36864
#define ATT_CS   (ATT_KSM + 36864)       // int cs[16]         = 64
#define SMEM_ATT (ATT_CS + 64)           // 112704
#define AROWB 528
#define VROWB 144

__global__ __launch_bounds__(256) void attn_kernel(const int* __restrict__ t,
                                                   const int* __restrict__ c,
                                                   float* __restrict__ out_target,
                                                   float* __restrict__ out_ctx)
{
    extern __shared__ char sm[];
    float (*Sc)[17] = (float(*)[17])(sm + ATT_SC);
    int* cs = (int*)(sm + ATT_CS);
    const uint32_t smb = smem_u32(sm);

    const int b    = blockIdx.x;
    const int tid  = threadIdx.x;
    const int lane = tid & 31;
    const int w    = tid >> 5;

    if (tid < SEQ) cs[tid] = c[b * SEQ + tid];

    // Q hi/lo split into smem (exact)
    {
        const int h = tid >> 4;
        const int d = (tid & 15) * 4;
        float4 v = *(const float4*)(g_Q + (size_t)b * HIDDEN + h * DHEAD + d);
        __half h0 = __float2half_rn(v.x), h1 = __float2half_rn(v.y);
        __half h2 = __float2half_rn(v.z), h3 = __float2half_rn(v.w);
        __half2* qh = (__half2*)(sm + ATT_QHI + h * VROWB + d * 2);
        __half2* ql = (__half2*)(sm + ATT_QLO + h * VROWB + d * 2);
        qh[0] = __halves2half2(h0, h1);
        qh[1] = __halves2half2(h2, h3);
        ql[0] = __halves2half2(__float2half_rn(v.x - __half2float(h0)),
                               __float2half_rn(v.y - __half2float(h1)));
        ql[1] = __halves2half2(__float2half_rn(v.z - __half2float(h2)),
                               __float2half_rn(v.w - __half2float(h3)));
    }

    // target_vector[b] = V-table row of token t[b]
    {
        const int tb = t[b];
        uint2 raw = ((const uint2*)(g_Vv + (size_t)tb * HIDDEN))[tid];
        float2 f0 = __half22float2(*(__half2*)&raw.x);
        float2 f1 = __half22float2(*(__half2*)&raw.y);
        *(float4*)(out_target + (size_t)b * HIDDEN + tid * 4) =
            make_float4(f0.x, f0.y, f1.x, f1.y);
    }
    __syncthreads();

    // K and V staging
#pragma unroll
    for (int j = 0; j < 16; j++) {
        const int idx = tid + j * 256;
        const int row = idx >> 4;
        const int cc  = idx & 15;
        const size_t gofs = (size_t)cs[row >> 4] * HIDDEN + (row & 15) * DHEAD + cc * 4;
        *(uint2*)(sm + ATT_KSM + row * VROWB + cc * 8) = *(const uint2*)(g_Kv + gofs);
        *(uint2*)(sm + ATT_VSM + row * VROWB + cc * 8) = *(const uint2*)(g_Vv + gofs);
    }
    __syncthreads();

    // scores via mma
    {
        const uint32_t aH = smb + ATT_QHI + (lane & 15) * VROWB + (lane >> 4) * 16;
        const uint32_t aL = smb + ATT_QLO + (lane & 15) * VROWB + (lane >> 4) * 16;
        uint32_t bB[2];
#pragma unroll
        for (int g16 = 0; g16 < 2; g16++)
            bB[g16] = smb + ATT_KSM
                    + (uint32_t)((w * 32 + g16 * 16 + (lane & 15)) * VROWB)
                    + (lane >> 4) * 16;

        float acc[2][2][4];
#pragma unroll
        for (int g16 = 0; g16 < 2; g16++)
#pragma unroll
            for (int j = 0; j < 2; j++)
#pragma unroll
                for (int q = 0; q < 4; q++) acc[g16][j][q] = 0.0f;

#pragma unroll
        for (int kk = 0; kk < 4; kk++) {
            uint32_t ah0, ah1, ah2, ah3, al0, al1, al2, al3;
            ldm4(ah0, ah1, ah2, ah3, aH + kk * 32);
            ldm4(al0, al1, al2, al3, aL + kk * 32);
#pragma unroll
            for (int g16 = 0; g16 < 2; g16++) {
                uint32_t b0, b1, b2, b3;
                ldm4(b0, b1, b2, b3, bB[g16] + kk * 32);
                mma16816(acc[g16][0], ah0, ah1, ah2, ah3, b0, b2);
                mma16816(acc[g16][1], ah0, ah1, ah2, ah3, b1, b3);
                mma16816(acc[g16][0], al0, al1, al2, al3, b0, b2);
                mma16816(acc[g16][1], al0, al1, al2, al3, b1, b3);
            }
        }

        const int h0 = lane >> 2;
#pragma unroll
        for (int g16 = 0; g16 < 2; g16++)
#pragma unroll
            for (int j = 0; j < 2; j++) {
                const int sg = w * 32 + g16 * 16 + j * 8 + (lane & 3) * 2;
                const int s = sg >> 4, g = sg & 15;
                const float* d = acc[g16][j];
                Sc[s * 16 + h0][g]     = d[0] * 0.125f;
                Sc[s * 16 + h0][g + 1] = d[1] * 0.125f;
                Sc[s * 16 + h0 + 8][g]     = d[2] * 0.125f;
                Sc[s * 16 + h0 + 8][g + 1] = d[3] * 0.125f;
            }
    }
    __syncthreads();

    // softmax + A hi/lo
    {
        const int s = tid >> 4, h = tid & 15;
        float v[16];
        float* row = Sc[tid];
        float mx = -1e30f;
#pragma unroll
        for (int g = 0; g < 16; g++) { v[g] = row[g]; mx = fmaxf(mx, v[g]); }
        float sum = 0.0f;
#pragma unroll
        for (int g = 0; g < 16; g++) { v[g] = __expf(v[g] - mx); sum += v[g]; }
        float inv = 1.0f / sum;
        __half2* dh = (__half2*)(sm + ATT_AHI + h * AROWB + s * 32);
        __half2* dl = (__half2*)(sm + ATT_ALO + h * AROWB + s * 32);
#pragma unroll
        for (int gp = 0; gp < 8; gp++) {
            float a0 = v[2 * gp] * inv, a1 = v[2 * gp + 1] * inv;
            __half h0 = __float2half_rn(a0), h1 = __float2half_rn(a1);
            float l0 = a0 - __half2float(h0), l1 = a1 - __half2float(h1);
            dh[gp] = __halves2half2(h0, h1);
            dl[gp] = __halves2half2(__float2half_rn(l0), __float2half_rn(l1));
        }
    }
    __syncthreads();

    // AV via mma
    {
        const uint32_t aH = smb + ATT_AHI + (lane & 15) * AROWB + (lane >> 4) * 16;
        const uint32_t aL = smb + ATT_ALO + (lane & 15) * AROWB + (lane >> 4) * 16;
        const uint32_t bB = smb + ATT_VSM + (lane & 15) * VROWB + w * 16;

        float acc[4] = {0.f, 0.f, 0.f, 0.f};
#pragma unroll
        for (int kk = 0; kk < 16; kk++) {
            uint32_t a0, a1, a2, a3, l0, l1, l2, l3, b0, b1;
            ldm4(a0, a1, a2, a3, aH + kk * 32);
            ldm4(l0, l1, l2, l3, aL + kk * 32);
            ldm2t(b0, b1, bB + kk * 16 * VROWB);
            mma16816(acc, a0, a1, a2, a3, b0, b1);
            mma16816(acc, l0, l1, l2, l3, b0, b1);
        }

        const int h0 = lane >> 2;
        const int dcol = w * 8 + (lane & 3) * 2;
        float* o = out_ctx + (size_t)b * HIDDEN;
        *(float2*)(o + h0 * DHEAD + dcol)       = make_float2(acc[0], acc[1]);
        *(float2*)(o + (h0 + 8) * DHEAD + dcol) = make_float2(acc[2], acc[3]);
    }
}

// ---------------------------------------------------------------------------
extern "C" void kernel_launch(void* const* d_in, const int* in_sizes, int n_in,
                              void* d_out, int out_size)
{
    const int*   t   = (const int*)d_in[0];
    const int*   c   = (const int*)d_in[1];
    const float* emb = (const float*)d_in[2];
    const float* WQ  = (const float*)d_in[3];
    const float* bQ  = (const float*)d_in[4];
    const float* WK  = (const float*)d_in[5];
    const float* bK  = (const float*)d_in[6];
    const float* WV  = (const float*)d_in[7];
    const float* bV  = (const float*)d_in[8];
    float* out = (float*)d_out;

    float* out_target = out;
    float* out_ctx    = out + (size_t)BATCH * HIDDEN;

    // fused: zero flags + convert emb + convert weights (one launch)
    {
        const int n4e = (VOCAB * EMBED) / 4;
        const int n4w = (HIDDEN * EMBED) / 4;
        const int total = n4e + 3 * n4w;
        prep_kernel<<<(total + 255) / 256, 256>>>(emb, WQ, WK, WV, n4e, n4w);
    }
    // compaction (c AND t)
    mark_kernel<<<(BATCH * SEQ + 255) / 256, 256>>>(c, t);
    compact_kernel<<<(VPAD + 255) / 256, 256>>>();

    // GEMMs: K/V for used tokens (scattered) + Q for targets
    cudaFuncSetAttribute(gemm_mma_kernel,
                         cudaFuncAttributeMaxDynamicSharedMemorySize, SMEM_DYN);
    {
        dim3 grid(16, NV_TILES + NT_TILES);
        gemm_mma_kernel<<<grid, 256, SMEM_DYN>>>(t, bQ, bK, bV);
    }

    // attention (all tensor-core) + target_vector gather
    cudaFuncSetAttribute(attn_kernel,
                         cudaFuncAttributeMaxDynamicSharedMemorySize, SMEM_ATT);
    attn_kernel<<<BATCH, 256, SMEM_ATT>>>(t, c, out_target, out_ctx);
}